// round 6
// baseline (speedup 1.0000x reference)
#include <cuda_runtime.h>
#include <math.h>

#define N_NODES 50000
#define N_EDGES 1600000
#define D 128
#define BN_EPS 1e-5f

// ---------------- device scratch (no allocations allowed) ----------------
__device__ __align__(16) float g_hws[N_NODES * D];  // h @ W   (unscaled)
__device__ __align__(16) float g_agg[N_NODES * D];  // pre-BN activations
__device__ __align__(16) float2 g_Wp[3 * D * D];    // W split {tf32 hi, tf32 lo}
__device__ int   g_src[N_EDGES];
__device__ int   g_dst[N_EDGES];
__device__ int   g_is_i32 = 0;                      // set-only dtype flag
__device__ int   g_deg[N_NODES];
__device__ int   g_rowstart[N_NODES + 1];
__device__ int   g_cursor[N_NODES];
__device__ int   g_csr_src[N_EDGES];
__device__ float g_csr_w[N_EDGES];                  // dinv[src]*dinv[dst]
__device__ float g_dinv[N_NODES];                   // rsqrt(deg+2)
__device__ float g_colsum[D];
__device__ float g_colsq[D];
__device__ float g_scale[D];
__device__ float g_shift[D];

// ---------------- helpers ----------------
__device__ __forceinline__ unsigned f2tf32(float x) {
    unsigned r;
    asm("cvt.rna.tf32.f32 %0, %1;" : "=r"(r) : "f"(x));
    return r;
}
__device__ __forceinline__ float2 split_tf32(float v) {
    float hi = __uint_as_float(f2tf32(v));
    float lo = __uint_as_float(f2tf32(v - hi));
    return make_float2(hi, lo);
}
__device__ __forceinline__ void mma_tf32(float c[4], const unsigned a[4],
                                         unsigned b0, unsigned b1) {
    asm volatile(
        "mma.sync.aligned.m16n8k8.row.col.f32.tf32.tf32.f32 "
        "{%0,%1,%2,%3}, {%4,%5,%6,%7}, {%8,%9}, {%0,%1,%2,%3};"
        : "+f"(c[0]), "+f"(c[1]), "+f"(c[2]), "+f"(c[3])
        : "r"(a[0]), "r"(a[1]), "r"(a[2]), "r"(a[3]), "r"(b0), "r"(b1));
}

// ---------------- preprocessing ----------------

// split all three W matrices into packed {hi,lo}
__global__ void wsplit_kernel(const float* __restrict__ W0,
                              const float* __restrict__ W1,
                              const float* __restrict__ W2) {
    int i = blockIdx.x * blockDim.x + threadIdx.x;
    if (i >= 3 * D * D) return;
    const float* Ws = (i < D * D) ? W0 : (i < 2 * D * D ? W1 : W2);
    g_Wp[i] = split_tf32(Ws[i & (D * D - 1)]);
}

// zero degree; detect int32-vs-int64 on first 8192 odd words
__global__ void detect_kernel(const int* __restrict__ p32) {
    int i = blockIdx.x * blockDim.x + threadIdx.x;
    if (i < N_NODES) g_deg[i] = 0;
    if (i < 8192 && p32[2 * i + 1] != 0) g_is_i32 = 1;
}

__global__ void convert_count_kernel(const void* __restrict__ eiv) {
    int e = blockIdx.x * blockDim.x + threadIdx.x;
    if (e >= N_EDGES) return;
    int s, d;
    if (g_is_i32) {
        const int* p = (const int*)eiv;
        s = p[e]; d = p[N_EDGES + e];
    } else {
        const long long* p = (const long long*)eiv;
        s = (int)p[e]; d = (int)p[N_EDGES + e];
    }
    g_src[e] = s;
    g_dst[e] = d;
    atomicAdd(&g_deg[d], 1);
}

// single-block exclusive scan of g_deg -> g_rowstart; dinv/cursor tail
__global__ void scan_final_kernel() {
    __shared__ int warpsum[32];
    __shared__ int s_carry;
    const int tid = threadIdx.x, lane = tid & 31, wid = tid >> 5;
    if (tid == 0) s_carry = 0;
    __syncthreads();

    for (int base = 0; base < N_NODES; base += 1024) {
        int i = base + tid;
        int v = (i < N_NODES) ? g_deg[i] : 0;
        int x = v;
#pragma unroll
        for (int off = 1; off < 32; off <<= 1) {
            int n = __shfl_up_sync(0xffffffffu, x, off);
            if (lane >= off) x += n;
        }
        if (lane == 31) warpsum[wid] = x;
        __syncthreads();
        if (wid == 0) {
            int w = warpsum[lane];
#pragma unroll
            for (int off = 1; off < 32; off <<= 1) {
                int n = __shfl_up_sync(0xffffffffu, w, off);
                if (lane >= off) w += n;
            }
            warpsum[lane] = w;
        }
        __syncthreads();
        int wprefix = (wid == 0) ? 0 : warpsum[wid - 1];
        int carry = s_carry;
        if (i < N_NODES) g_rowstart[i] = carry + x + wprefix - v;  // exclusive
        int total = warpsum[31];
        __syncthreads();
        if (tid == 0) s_carry = carry + total;
        __syncthreads();
    }
    if (tid == 0) g_rowstart[N_NODES] = s_carry;
    __syncthreads();
    for (int i = tid; i < N_NODES; i += 1024) {
        float dd = (float)g_deg[i] + 2.0f;
        g_dinv[i] = rsqrtf(dd);
        g_cursor[i] = g_rowstart[i];
    }
}

__global__ void fill_kernel() {
    int e = blockIdx.x * blockDim.x + threadIdx.x;
    if (e < N_EDGES) {
        int s = g_src[e], d = g_dst[e];
        int p = atomicAdd(&g_cursor[d], 1);
        g_csr_src[p] = s;
        g_csr_w[p] = g_dinv[s] * g_dinv[d];
    }
}

// ---------------- GEMM: split-tf32 mma.sync, 32 rows x 128 cols / block ----
// mode 0: input = A (x). mode 1: input = ReLU(g_agg*scale+shift).
// Block 64 threads = 2 warps; warp handles 16 rows. Block 0 zeroes BN stats.
__global__ void __launch_bounds__(64) gemm_kernel(const float* __restrict__ A,
                                                  const float2* __restrict__ Wp,
                                                  int mode) {
    __shared__ float2 sA[32][132];          // {hi,lo} per element, padded
    __shared__ float s_scale[D], s_shift[D];
    const int tid = threadIdx.x;
    const int rb = blockIdx.x * 32;

    if (mode) {
        s_scale[tid] = g_scale[tid];       s_shift[tid] = g_shift[tid];
        s_scale[tid + 64] = g_scale[tid + 64]; s_shift[tid + 64] = g_shift[tid + 64];
    }
    if (blockIdx.x == 0) {
        g_colsum[tid] = 0.0f; g_colsum[tid + 64] = 0.0f;
        g_colsq[tid] = 0.0f;  g_colsq[tid + 64] = 0.0f;
    }
    __syncthreads();

    // stage + split 32x128 fp32 into sA
#pragma unroll
    for (int it = 0; it < 16; it++) {
        int v4 = it * 64 + tid;            // 0..1023 float4 slots
        int row = v4 >> 5;
        int c4 = (v4 & 31) << 2;
        int grow = rb + row;
        float4 a = make_float4(0.f, 0.f, 0.f, 0.f);
        if (grow < N_NODES) {
            const float4* src = (const float4*)((mode ? g_agg : A) + grow * D);
            a = src[v4 & 31];
            if (mode) {
                a.x = fmaxf(a.x * s_scale[c4 + 0] + s_shift[c4 + 0], 0.f);
                a.y = fmaxf(a.y * s_scale[c4 + 1] + s_shift[c4 + 1], 0.f);
                a.z = fmaxf(a.z * s_scale[c4 + 2] + s_shift[c4 + 2], 0.f);
                a.w = fmaxf(a.w * s_scale[c4 + 3] + s_shift[c4 + 3], 0.f);
            }
        }
        sA[row][c4 + 0] = split_tf32(a.x);
        sA[row][c4 + 1] = split_tf32(a.y);
        sA[row][c4 + 2] = split_tf32(a.z);
        sA[row][c4 + 3] = split_tf32(a.w);
    }
    __syncthreads();

    const int wid = tid >> 5;              // 0..1
    const int lane = tid & 31;
    const int grp = lane >> 2, t4 = lane & 3;
    const int wr = wid * 16;

    float c[16][4];
#pragma unroll
    for (int n0 = 0; n0 < 16; n0++) {
        c[n0][0] = 0.f; c[n0][1] = 0.f; c[n0][2] = 0.f; c[n0][3] = 0.f;
    }

#pragma unroll 1
    for (int k0 = 0; k0 < 16; k0++) {
        const int kc = k0 * 8 + t4;
        float2 A0 = sA[wr + grp][kc];
        float2 A1 = sA[wr + grp + 8][kc];
        float2 A2 = sA[wr + grp][kc + 4];
        float2 A3 = sA[wr + grp + 8][kc + 4];
        unsigned ah[4] = {__float_as_uint(A0.x), __float_as_uint(A1.x),
                          __float_as_uint(A2.x), __float_as_uint(A3.x)};
        unsigned al[4] = {__float_as_uint(A0.y), __float_as_uint(A1.y),
                          __float_as_uint(A2.y), __float_as_uint(A3.y)};
        const float2* wp = Wp + kc * D + grp;       // b0: (k=kc,   n=n0*8+grp)
        const float2* wp4 = wp + 4 * D;             // b1: (k=kc+4, n=n0*8+grp)
#pragma unroll
        for (int n0 = 0; n0 < 16; n0++) {
            float2 B0 = wp[n0 * 8];
            float2 B1 = wp4[n0 * 8];
            unsigned b0h = __float_as_uint(B0.x), b0l = __float_as_uint(B0.y);
            unsigned b1h = __float_as_uint(B1.x), b1l = __float_as_uint(B1.y);
            mma_tf32(c[n0], ah, b0h, b1h);   // hi*hi
            mma_tf32(c[n0], ah, b0l, b1l);   // hi*lo
            mma_tf32(c[n0], al, b0h, b1h);   // lo*hi
        }
    }

    // epilogue: c0=(g,2t4) c1=(g,2t4+1) c2=(g+8,2t4) c3=(g+8,2t4+1)
    const int row0 = rb + wr + grp;
    const int row1 = row0 + 8;
#pragma unroll
    for (int n0 = 0; n0 < 16; n0++) {
        int n = n0 * 8 + 2 * t4;
        if (row0 < N_NODES)
            *(float2*)&g_hws[row0 * D + n] = make_float2(c[n0][0], c[n0][1]);
        if (row1 < N_NODES)
            *(float2*)&g_hws[row1 * D + n] = make_float2(c[n0][2], c[n0][3]);
    }
}

// ---------------- aggregate (warp per node) + fused BN stats ----------------
__global__ void aggregate_kernel(const float* __restrict__ b) {
    __shared__ float4 s_s[8][32];
    __shared__ float4 s_q[8][32];
    const int w = threadIdx.x >> 5;
    const int lane = threadIdx.x & 31;
    const int node = blockIdx.x * 8 + w;

    float4 o = make_float4(0.f, 0.f, 0.f, 0.f);
    if (node < N_NODES) {
        const int beg = g_rowstart[node];
        const int end = g_rowstart[node + 1];
        const float4* __restrict__ hws4 = reinterpret_cast<const float4*>(g_hws);

        float4 acc = make_float4(0.f, 0.f, 0.f, 0.f);
        for (int k0 = beg; k0 < end; k0 += 32) {
            int t = k0 + lane;
            int idx = 0; float wt = 0.f;
            if (t < end) { idx = g_csr_src[t]; wt = g_csr_w[t]; }
            int m = min(32, end - k0);
#pragma unroll 8
            for (int j = 0; j < m; j++) {
                int s = __shfl_sync(0xffffffffu, idx, j);
                float ww = __shfl_sync(0xffffffffu, wt, j);
                float4 v = hws4[s * 32 + lane];
                acc.x += ww * v.x; acc.y += ww * v.y;
                acc.z += ww * v.z; acc.w += ww * v.w;
            }
        }
        float4 self = hws4[node * 32 + lane];
        float di = g_dinv[node];
        float sw = 2.0f * di * di;
        float4 b4 = reinterpret_cast<const float4*>(b)[lane];
        o.x = acc.x + sw * self.x + b4.x;
        o.y = acc.y + sw * self.y + b4.y;
        o.z = acc.z + sw * self.z + b4.z;
        o.w = acc.w + sw * self.w + b4.w;
        reinterpret_cast<float4*>(g_agg)[node * 32 + lane] = o;
    }

    s_s[w][lane] = o;
    s_q[w][lane] = make_float4(o.x * o.x, o.y * o.y, o.z * o.z, o.w * o.w);
    __syncthreads();
    if (threadIdx.x < 32) {
        float4 ss = make_float4(0.f, 0.f, 0.f, 0.f);
        float4 qq = make_float4(0.f, 0.f, 0.f, 0.f);
#pragma unroll
        for (int i = 0; i < 8; i++) {
            float4 a = s_s[i][lane], q = s_q[i][lane];
            ss.x += a.x; ss.y += a.y; ss.z += a.z; ss.w += a.w;
            qq.x += q.x; qq.y += q.y; qq.z += q.z; qq.w += q.w;
        }
        int c = 4 * lane;
        atomicAdd(&g_colsum[c + 0], ss.x); atomicAdd(&g_colsum[c + 1], ss.y);
        atomicAdd(&g_colsum[c + 2], ss.z); atomicAdd(&g_colsum[c + 3], ss.w);
        atomicAdd(&g_colsq[c + 0], qq.x);  atomicAdd(&g_colsq[c + 1], qq.y);
        atomicAdd(&g_colsq[c + 2], qq.z);  atomicAdd(&g_colsq[c + 3], qq.w);
    }
}

__global__ void bn_final_kernel(const float* __restrict__ gamma,
                                const float* __restrict__ beta) {
    int c = threadIdx.x;
    float mean = g_colsum[c] * (1.0f / (float)N_NODES);
    float var = g_colsq[c] * (1.0f / (float)N_NODES) - mean * mean;
    float sc = gamma[c] * rsqrtf(var + BN_EPS);
    g_scale[c] = sc;
    g_shift[c] = beta[c] - mean * sc;
}

// final layer: out = relu(agg*scale + shift)
__global__ void apply_kernel(float* __restrict__ out) {
    int idx = blockIdx.x * blockDim.x + threadIdx.x;
    if (idx >= N_NODES * D) return;
    int c = idx & (D - 1);
    float v = g_agg[idx] * g_scale[c] + g_shift[c];
    out[idx] = fmaxf(v, 0.0f);
}

// ---------------- launch ----------------
extern "C" void kernel_launch(void* const* d_in, const int* in_sizes, int n_in,
                              void* d_out, int out_size) {
    const float* x = (const float*)d_in[0];
    const void* ei = d_in[1];
    const float* W[3]  = {(const float*)d_in[2],  (const float*)d_in[6],  (const float*)d_in[10]};
    const float* bb[3] = {(const float*)d_in[3],  (const float*)d_in[7],  (const float*)d_in[11]};
    const float* gg[3] = {(const float*)d_in[4],  (const float*)d_in[8],  (const float*)d_in[12]};
    const float* be[3] = {(const float*)d_in[5],  (const float*)d_in[9],  (const float*)d_in[13]};
    float* out = (float*)d_out;

    const int eblocks = (N_EDGES + 255) / 256;
    const int nblocks = (N_NODES + 255) / 256;
    const int gemm_blocks = (N_NODES + 31) / 32;
    const int agg_blocks = (N_NODES + 7) / 8;
    const int app_blocks = (N_NODES * D + 255) / 256;

    float2* Wp;
    cudaGetSymbolAddress((void**)&Wp, g_Wp);

    wsplit_kernel<<<(3 * D * D + 255) / 256, 256>>>(W[0], W[1], W[2]);  // 1
    detect_kernel<<<nblocks, 256>>>((const int*)ei);                    // 2
    convert_count_kernel<<<eblocks, 256>>>(ei);                         // 3
    gemm_kernel<<<gemm_blocks, 64>>>(x, Wp, 0);                         // 4 <- ncu
    scan_final_kernel<<<1, 1024>>>();                                   // 5
    fill_kernel<<<eblocks, 256>>>();                                    // 6

    for (int layer = 0; layer < 3; layer++) {
        if (layer > 0)
            gemm_kernel<<<gemm_blocks, 64>>>(x, Wp + layer * D * D, 1);
        aggregate_kernel<<<agg_blocks, 256>>>(bb[layer]);
        bn_final_kernel<<<1, D>>>(gg[layer], be[layer]);
    }
    apply_kernel<<<app_blocks, 256>>>(out);
}

// round 7
// speedup vs baseline: 2.3890x; 2.3890x over previous
#include <cuda_runtime.h>
#include <cuda_fp16.h>
#include <math.h>

#define N_NODES 50000
#define N_EDGES 1600000
#define D 128
#define BN_EPS 1e-5f

// ---------------- device scratch (no allocations allowed) ----------------
__device__ __align__(16) float  g_hws[N_NODES * D];   // (h @ W) * dinv[row], fp32
__device__ __align__(16) __half g_hws_h[N_NODES * D]; // same, fp16 (gather copy)
__device__ __align__(16) float  g_agg[N_NODES * D];   // pre-BN activations
__device__ int   g_src[N_EDGES];
__device__ int   g_dst[N_EDGES];
__device__ int   g_is_i32 = 0;                        // set-only dtype flag
__device__ int   g_deg[N_NODES];
__device__ int   g_rowstart[N_NODES + 1];
__device__ int   g_cursor[N_NODES];
__device__ int   g_csr_src[N_EDGES];
__device__ float g_dinv[N_NODES];                     // rsqrt(deg+2)
__device__ float g_colsum[D];
__device__ float g_colsq[D];
__device__ float g_scale[D];
__device__ float g_shift[D];

// ---------------- input canonicalization + degree zero ----------------
// int64 little-endian with values<2^31 -> odd 32-bit words are 0.
// int32 -> odd words are random nonzero indices. Flag is set-only.
__global__ void detect_kernel(const int* __restrict__ p32) {
    int i = blockIdx.x * blockDim.x + threadIdx.x;
    if (i < N_NODES) g_deg[i] = 0;
    if (i < 8192 && p32[2 * i + 1] != 0) g_is_i32 = 1;
}

__global__ void convert_count_kernel(const void* __restrict__ eiv) {
    int e = blockIdx.x * blockDim.x + threadIdx.x;
    if (e >= N_EDGES) return;
    int s, d;
    if (g_is_i32) {
        const int* p = (const int*)eiv;
        s = p[e]; d = p[N_EDGES + e];
    } else {
        const long long* p = (const long long*)eiv;
        s = (int)p[e]; d = (int)p[N_EDGES + e];
    }
    g_src[e] = s;
    g_dst[e] = d;
    atomicAdd(&g_deg[d], 1);
}

// single-block exclusive scan of g_deg -> g_rowstart; dinv/cursor tail
__global__ void scan_final_kernel() {
    __shared__ int warpsum[32];
    __shared__ int s_carry;
    const int tid = threadIdx.x, lane = tid & 31, wid = tid >> 5;
    if (tid == 0) s_carry = 0;
    __syncthreads();

    for (int base = 0; base < N_NODES; base += 1024) {
        int i = base + tid;
        int v = (i < N_NODES) ? g_deg[i] : 0;
        int x = v;
#pragma unroll
        for (int off = 1; off < 32; off <<= 1) {
            int n = __shfl_up_sync(0xffffffffu, x, off);
            if (lane >= off) x += n;
        }
        if (lane == 31) warpsum[wid] = x;
        __syncthreads();
        if (wid == 0) {
            int w = warpsum[lane];
#pragma unroll
            for (int off = 1; off < 32; off <<= 1) {
                int n = __shfl_up_sync(0xffffffffu, w, off);
                if (lane >= off) w += n;
            }
            warpsum[lane] = w;
        }
        __syncthreads();
        int wprefix = (wid == 0) ? 0 : warpsum[wid - 1];
        int carry = s_carry;
        if (i < N_NODES) g_rowstart[i] = carry + x + wprefix - v;  // exclusive
        int total = warpsum[31];
        __syncthreads();
        if (tid == 0) s_carry = carry + total;
        __syncthreads();
    }
    if (tid == 0) g_rowstart[N_NODES] = s_carry;
    __syncthreads();
    for (int i = tid; i < N_NODES; i += 1024) {
        float dd = (float)g_deg[i] + 2.0f;
        g_dinv[i] = rsqrtf(dd);
        g_cursor[i] = g_rowstart[i];
    }
}

__global__ void fill_kernel() {
    int e = blockIdx.x * blockDim.x + threadIdx.x;
    if (e < N_EDGES) {
        int p = atomicAdd(&g_cursor[g_dst[e]], 1);
        g_csr_src[p] = g_src[e];
    }
}

// ---------------- per-layer kernels ----------------

// hws = f(src) @ W * dinv[row].  mode 0: f = identity on x.
// mode 1: f = ReLU(g_agg*scale+shift) (fused BN apply of previous layer).
// Block: 128 threads (one per column), 32 rows. Block 0 also zeroes BN stats.
// Writes fp32 hws AND pair-packed fp16 copy.
__global__ void gemm_kernel(const float* __restrict__ A, const float* __restrict__ W,
                            int mode) {
    __shared__ __align__(16) float shA[32][D];
    const int rb = blockIdx.x * 32;
    const int t = threadIdx.x;  // column 0..127

    float sc = 0.0f, sh = 0.0f;
    if (mode) { sc = g_scale[t]; sh = g_shift[t]; }

#pragma unroll
    for (int r = 0; r < 32; r++) {
        int row = rb + r;
        float v = 0.0f;
        if (row < N_NODES) {
            if (mode) {
                v = g_agg[row * D + t];
                v = fmaxf(v * sc + sh, 0.0f);
            } else {
                v = A[row * D + t];
            }
        }
        shA[r][t] = v;
    }
    if (blockIdx.x == 0) { g_colsum[t] = 0.0f; g_colsq[t] = 0.0f; }
    __syncthreads();

    float acc[32];
#pragma unroll
    for (int r = 0; r < 32; r++) acc[r] = 0.0f;

    const float4* shA4 = reinterpret_cast<const float4*>(&shA[0][0]);
#pragma unroll 4
    for (int k4 = 0; k4 < D / 4; k4++) {
        float4 w4;
        w4.x = W[(4 * k4 + 0) * D + t];
        w4.y = W[(4 * k4 + 1) * D + t];
        w4.z = W[(4 * k4 + 2) * D + t];
        w4.w = W[(4 * k4 + 3) * D + t];
#pragma unroll
        for (int r = 0; r < 32; r++) {
            float4 a = shA4[r * (D / 4) + k4];
            acc[r] += a.x * w4.x;
            acc[r] += a.y * w4.y;
            acc[r] += a.z * w4.z;
            acc[r] += a.w * w4.w;
        }
    }

    __half2* hout = reinterpret_cast<__half2*>(g_hws_h);
#pragma unroll
    for (int r = 0; r < 32; r++) {
        int row = rb + r;
        float val = (row < N_NODES) ? acc[r] * g_dinv[row] : 0.0f;
        float vnx = __shfl_down_sync(0xffffffffu, val, 1);
        if (row < N_NODES) {
            g_hws[row * D + t] = val;
            if ((t & 1) == 0)
                hout[row * (D / 2) + (t >> 1)] = __floats2half2_rn(val, vnx);
        }
    }
}

// warp per node; lane owns 4 columns. fp16 gathers (256B/row), fp32 accum.
// Indices prefetched 32 at a time, shfl-broadcast. (R5 structure: no block
// barrier, early exit, single shfl stream.)
__global__ void aggregate_kernel(const float* __restrict__ b) {
    const int node = blockIdx.x * 8 + (threadIdx.x >> 5);
    const int lane = threadIdx.x & 31;
    if (node >= N_NODES) return;

    const int beg = g_rowstart[node];
    const int end = g_rowstart[node + 1];
    const uint2* __restrict__ hh = reinterpret_cast<const uint2*>(g_hws_h);

    float4 acc = make_float4(0.0f, 0.0f, 0.0f, 0.0f);
    for (int k0 = beg; k0 < end; k0 += 32) {
        int t = k0 + lane;
        int idx = (t < end) ? g_csr_src[t] : 0;
        int m = min(32, end - k0);
#pragma unroll 8
        for (int j = 0; j < m; j++) {
            int s = __shfl_sync(0xffffffffu, idx, j);
            uint2 raw = hh[s * 32 + lane];          // 4 halfs = cols 4lane..4lane+3
            float2 f0 = __half22float2(*reinterpret_cast<__half2*>(&raw.x));
            float2 f1 = __half22float2(*reinterpret_cast<__half2*>(&raw.y));
            acc.x += f0.x; acc.y += f0.y; acc.z += f1.x; acc.w += f1.y;
        }
    }

    const float4* __restrict__ hws4 = reinterpret_cast<const float4*>(g_hws);
    float4 self = hws4[node * 32 + lane];           // fp32 self term
    float dinv = g_dinv[node];
    float4 b4 = reinterpret_cast<const float4*>(b)[lane];
    float4 o;
    o.x = dinv * (acc.x + 2.0f * self.x) + b4.x;
    o.y = dinv * (acc.y + 2.0f * self.y) + b4.y;
    o.z = dinv * (acc.z + 2.0f * self.z) + b4.z;
    o.w = dinv * (acc.w + 2.0f * self.w) + b4.w;
    reinterpret_cast<float4*>(g_agg)[node * 32 + lane] = o;
}

// column sums/sumsq over g_agg; block handles 128 rows (thread = column)
__global__ void stats_kernel() {
    const int c = threadIdx.x;
    const int r0 = blockIdx.x * 128;
    float s = 0.0f, sq = 0.0f;
    for (int i = 0; i < 128; i++) {
        int r = r0 + i;
        if (r >= N_NODES) break;
        float v = g_agg[r * D + c];
        s += v;
        sq += v * v;
    }
    atomicAdd(&g_colsum[c], s);
    atomicAdd(&g_colsq[c], sq);
}

__global__ void bn_final_kernel(const float* __restrict__ gamma,
                                const float* __restrict__ beta) {
    int c = threadIdx.x;
    float mean = g_colsum[c] * (1.0f / (float)N_NODES);
    float var = g_colsq[c] * (1.0f / (float)N_NODES) - mean * mean;
    float sc = gamma[c] * rsqrtf(var + BN_EPS);
    g_scale[c] = sc;
    g_shift[c] = beta[c] - mean * sc;
}

// final layer only: out = relu(agg*scale + shift)
__global__ void apply_kernel(float* __restrict__ out) {
    int idx = blockIdx.x * blockDim.x + threadIdx.x;
    if (idx >= N_NODES * D) return;
    int c = idx & (D - 1);
    float v = g_agg[idx] * g_scale[c] + g_shift[c];
    out[idx] = fmaxf(v, 0.0f);
}

// ---------------- launch ----------------
extern "C" void kernel_launch(void* const* d_in, const int* in_sizes, int n_in,
                              void* d_out, int out_size) {
    const float* x = (const float*)d_in[0];
    const void* ei = d_in[1];
    const float* W[3]  = {(const float*)d_in[2],  (const float*)d_in[6],  (const float*)d_in[10]};
    const float* bb[3] = {(const float*)d_in[3],  (const float*)d_in[7],  (const float*)d_in[11]};
    const float* gg[3] = {(const float*)d_in[4],  (const float*)d_in[8],  (const float*)d_in[12]};
    const float* be[3] = {(const float*)d_in[5],  (const float*)d_in[9],  (const float*)d_in[13]};
    float* out = (float*)d_out;

    const int eblocks = (N_EDGES + 255) / 256;
    const int nblocks = (N_NODES + 255) / 256;
    const int gemm_blocks = (N_NODES + 31) / 32;
    const int agg_blocks = (N_NODES + 7) / 8;
    const int stats_blocks = (N_NODES + 127) / 128;
    const int app_blocks = (N_NODES * D + 255) / 256;

    detect_kernel<<<eblocks, 256>>>((const int*)ei);            // 1
    convert_count_kernel<<<eblocks, 256>>>(ei);                 // 2
    scan_final_kernel<<<1, 1024>>>();                           // 3
    gemm_kernel<<<gemm_blocks, 128>>>(x, W[0], 0);              // 4 <- ncu slot
    fill_kernel<<<eblocks, 256>>>();                            // 5

    for (int layer = 0; layer < 3; layer++) {
        if (layer > 0)
            gemm_kernel<<<gemm_blocks, 128>>>(x, W[layer], 1);
        aggregate_kernel<<<agg_blocks, 256>>>(bb[layer]);
        stats_kernel<<<stats_blocks, 128>>>();
        bn_final_kernel<<<1, D>>>(gg[layer], be[layer]);
    }
    apply_kernel<<<app_blocks, 256>>>(out);
}

// round 9
// speedup vs baseline: 2.6225x; 1.0978x over previous
#include <cuda_runtime.h>
#include <cuda_fp16.h>
#include <math.h>

#define N_NODES 50000
#define N_EDGES 1600000
#define D 128
#define BN_EPS 1e-5f

// ---------------- device scratch (no allocations allowed) ----------------
__device__ __align__(16) float  g_hws[N_NODES * D];   // (h @ W) * dinv[row], fp32
__device__ __align__(16) __half g_hws_h[N_NODES * D]; // same, fp16 (gather copy)
__device__ __align__(16) float  g_agg[N_NODES * D];   // pre-BN activations
__device__ int   g_src[N_EDGES];
__device__ int   g_dst[N_EDGES];
__device__ int   g_is_i32 = 0;                        // set-only dtype flag
__device__ int   g_deg[N_NODES];
__device__ int   g_rowstart[N_NODES + 1];
__device__ int   g_cursor[N_NODES];
__device__ int   g_csr_src[N_EDGES];
__device__ float g_dinv[N_NODES];                     // rsqrt(deg+2)
__device__ float g_colsum[D];
__device__ float g_colsq[D];
__device__ float g_scale[D];
__device__ float g_shift[D];

// ---------------- input canonicalization + degree zero ----------------
__global__ void detect_kernel(const int* __restrict__ p32) {
    int i = blockIdx.x * blockDim.x + threadIdx.x;
    if (i < N_NODES) g_deg[i] = 0;
    if (i < 8192 && p32[2 * i + 1] != 0) g_is_i32 = 1;
}

__global__ void convert_count_kernel(const void* __restrict__ eiv) {
    int e = blockIdx.x * blockDim.x + threadIdx.x;
    if (e >= N_EDGES) return;
    int s, d;
    if (g_is_i32) {
        const int* p = (const int*)eiv;
        s = p[e]; d = p[N_EDGES + e];
    } else {
        const long long* p = (const long long*)eiv;
        s = (int)p[e]; d = (int)p[N_EDGES + e];
    }
    g_src[e] = s;
    g_dst[e] = d;
    atomicAdd(&g_deg[d], 1);
}

// single-block exclusive scan of g_deg -> g_rowstart; dinv/cursor tail
__global__ void scan_final_kernel() {
    __shared__ int warpsum[32];
    __shared__ int s_carry;
    const int tid = threadIdx.x, lane = tid & 31, wid = tid >> 5;
    if (tid == 0) s_carry = 0;
    __syncthreads();

    for (int base = 0; base < N_NODES; base += 1024) {
        int i = base + tid;
        int v = (i < N_NODES) ? g_deg[i] : 0;
        int x = v;
#pragma unroll
        for (int off = 1; off < 32; off <<= 1) {
            int n = __shfl_up_sync(0xffffffffu, x, off);
            if (lane >= off) x += n;
        }
        if (lane == 31) warpsum[wid] = x;
        __syncthreads();
        if (wid == 0) {
            int w = warpsum[lane];
#pragma unroll
            for (int off = 1; off < 32; off <<= 1) {
                int n = __shfl_up_sync(0xffffffffu, w, off);
                if (lane >= off) w += n;
            }
            warpsum[lane] = w;
        }
        __syncthreads();
        int wprefix = (wid == 0) ? 0 : warpsum[wid - 1];
        int carry = s_carry;
        if (i < N_NODES) g_rowstart[i] = carry + x + wprefix - v;  // exclusive
        int total = warpsum[31];
        __syncthreads();
        if (tid == 0) s_carry = carry + total;
        __syncthreads();
    }
    if (tid == 0) g_rowstart[N_NODES] = s_carry;
    __syncthreads();
    for (int i = tid; i < N_NODES; i += 1024) {
        float dd = (float)g_deg[i] + 2.0f;
        g_dinv[i] = rsqrtf(dd);
        g_cursor[i] = g_rowstart[i];
    }
}

__global__ void fill_kernel() {
    int e = blockIdx.x * blockDim.x + threadIdx.x;
    if (e < N_EDGES) {
        int p = atomicAdd(&g_cursor[g_dst[e]], 1);
        g_csr_src[p] = g_src[e];
    }
}

// ---------------- register-tiled GEMM --------------------------------------
// tile: 64 rows x 128 cols, 256 threads, 4x8 micro-tile, K staged 8 deep.
// mode 0: input = A (x). mode 1: input = ReLU(g_agg*scale+shift).
// Epilogue: hws = acc*dinv[row] (fp32) + packed fp16 copy. Block 0 zeroes stats.
__global__ void __launch_bounds__(256) gemm_kernel(const float* __restrict__ A,
                                                   const float* __restrict__ W,
                                                   int mode) {
    __shared__ float sA[8][68];    // k-major A slice, padded
    __shared__ float sW[8][132];   // W slice, padded
    __shared__ float s_scale[D], s_shift[D];

    const int tid = threadIdx.x;
    const int rb = blockIdx.x * 64;
    const int tx = tid & 15;          // 0..15 -> col groups tx*4, 64+tx*4
    const int ty = tid >> 4;          // 0..15 -> rows ty*4..ty*4+3

    if (mode && tid < D) { s_scale[tid] = g_scale[tid]; s_shift[tid] = g_shift[tid]; }
    if (blockIdx.x == 0 && tid < D) { g_colsum[tid] = 0.0f; g_colsq[tid] = 0.0f; }
    __syncthreads();   // s_scale/s_shift visible to ALL warps before staging reads

    float c[4][8];
#pragma unroll
    for (int i = 0; i < 4; i++)
#pragma unroll
        for (int j = 0; j < 8; j++) c[i][j] = 0.0f;

    // staging roles
    const int a_row = tid >> 1;            // tid<128: row 0..63
    const int a_k4 = (tid & 1) * 4;        // k offset 0 or 4
    const int w_k = tid >> 5;              // 0..7
    const int w_c4 = (tid & 31) * 4;       // col 0..124

    const float* __restrict__ srcA = mode ? g_agg : A;

    for (int kk = 0; kk < D; kk += 8) {
        // ---- stage A (64x8, transposed to k-major) ----
        if (tid < 128) {
            int grow = rb + a_row;
            float4 a = make_float4(0.f, 0.f, 0.f, 0.f);
            if (grow < N_NODES) {
                a = *(const float4*)&srcA[grow * D + kk + a_k4];
                if (mode) {
                    int cb = kk + a_k4;
                    a.x = fmaxf(a.x * s_scale[cb + 0] + s_shift[cb + 0], 0.f);
                    a.y = fmaxf(a.y * s_scale[cb + 1] + s_shift[cb + 1], 0.f);
                    a.z = fmaxf(a.z * s_scale[cb + 2] + s_shift[cb + 2], 0.f);
                    a.w = fmaxf(a.w * s_scale[cb + 3] + s_shift[cb + 3], 0.f);
                }
            }
            sA[a_k4 + 0][a_row] = a.x;
            sA[a_k4 + 1][a_row] = a.y;
            sA[a_k4 + 2][a_row] = a.z;
            sA[a_k4 + 3][a_row] = a.w;
        }
        // ---- stage W (8x128, direct) ----
        *(float4*)&sW[w_k][w_c4] = *(const float4*)&W[(kk + w_k) * D + w_c4];
        __syncthreads();

#pragma unroll
        for (int k = 0; k < 8; k++) {
            float4 a0 = *(const float4*)&sA[k][ty * 4];
            float4 b0 = *(const float4*)&sW[k][tx * 4];
            float4 b1 = *(const float4*)&sW[k][64 + tx * 4];
            float av[4] = {a0.x, a0.y, a0.z, a0.w};
            float bv[8] = {b0.x, b0.y, b0.z, b0.w, b1.x, b1.y, b1.z, b1.w};
#pragma unroll
            for (int i = 0; i < 4; i++)
#pragma unroll
                for (int j = 0; j < 8; j++) c[i][j] += av[i] * bv[j];
        }
        __syncthreads();
    }

    // ---- epilogue ----
    __half2* hout = reinterpret_cast<__half2*>(g_hws_h);
#pragma unroll
    for (int i = 0; i < 4; i++) {
        int row = rb + ty * 4 + i;
        if (row >= N_NODES) break;
        float di = g_dinv[row];
        float4 lo = make_float4(c[i][0] * di, c[i][1] * di, c[i][2] * di, c[i][3] * di);
        float4 hi = make_float4(c[i][4] * di, c[i][5] * di, c[i][6] * di, c[i][7] * di);
        *(float4*)&g_hws[row * D + tx * 4] = lo;
        *(float4*)&g_hws[row * D + 64 + tx * 4] = hi;
        int hb = row * (D / 2);
        hout[hb + tx * 2]     = __floats2half2_rn(lo.x, lo.y);
        hout[hb + tx * 2 + 1] = __floats2half2_rn(lo.z, lo.w);
        hout[hb + 32 + tx * 2]     = __floats2half2_rn(hi.x, hi.y);
        hout[hb + 32 + tx * 2 + 1] = __floats2half2_rn(hi.z, hi.w);
    }
}

// ---------------- aggregate (warp per node, fp16 gathers) -------------------
__global__ void aggregate_kernel(const float* __restrict__ b) {
    const int node = blockIdx.x * 8 + (threadIdx.x >> 5);
    const int lane = threadIdx.x & 31;
    if (node >= N_NODES) return;

    const int beg = g_rowstart[node];
    const int end = g_rowstart[node + 1];
    const uint2* __restrict__ hh = reinterpret_cast<const uint2*>(g_hws_h);

    float4 acc = make_float4(0.0f, 0.0f, 0.0f, 0.0f);
    for (int k0 = beg; k0 < end; k0 += 32) {
        int t = k0 + lane;
        int idx = (t < end) ? g_csr_src[t] : 0;
        int m = min(32, end - k0);
#pragma unroll 8
        for (int j = 0; j < m; j++) {
            int s = __shfl_sync(0xffffffffu, idx, j);
            uint2 raw = hh[s * 32 + lane];
            float2 f0 = __half22float2(*reinterpret_cast<__half2*>(&raw.x));
            float2 f1 = __half22float2(*reinterpret_cast<__half2*>(&raw.y));
            acc.x += f0.x; acc.y += f0.y; acc.z += f1.x; acc.w += f1.y;
        }
    }

    const float4* __restrict__ hws4 = reinterpret_cast<const float4*>(g_hws);
    float4 self = hws4[node * 32 + lane];
    float dinv = g_dinv[node];
    float4 b4 = reinterpret_cast<const float4*>(b)[lane];
    float4 o;
    o.x = dinv * (acc.x + 2.0f * self.x) + b4.x;
    o.y = dinv * (acc.y + 2.0f * self.y) + b4.y;
    o.z = dinv * (acc.z + 2.0f * self.z) + b4.z;
    o.w = dinv * (acc.w + 2.0f * self.w) + b4.w;
    reinterpret_cast<float4*>(g_agg)[node * 32 + lane] = o;
}

// column sums/sumsq over g_agg; block handles 128 rows (thread = column)
__global__ void stats_kernel() {
    const int c = threadIdx.x;
    const int r0 = blockIdx.x * 128;
    float s = 0.0f, sq = 0.0f;
    for (int i = 0; i < 128; i++) {
        int r = r0 + i;
        if (r >= N_NODES) break;
        float v = g_agg[r * D + c];
        s += v;
        sq += v * v;
    }
    atomicAdd(&g_colsum[c], s);
    atomicAdd(&g_colsq[c], sq);
}

__global__ void bn_final_kernel(const float* __restrict__ gamma,
                                const float* __restrict__ beta) {
    int c = threadIdx.x;
    float mean = g_colsum[c] * (1.0f / (float)N_NODES);
    float var = g_colsq[c] * (1.0f / (float)N_NODES) - mean * mean;
    float sc = gamma[c] * rsqrtf(var + BN_EPS);
    g_scale[c] = sc;
    g_shift[c] = beta[c] - mean * sc;
}

// final layer only: out = relu(agg*scale + shift)
__global__ void apply_kernel(float* __restrict__ out) {
    int idx = blockIdx.x * blockDim.x + threadIdx.x;
    if (idx >= N_NODES * D) return;
    int c = idx & (D - 1);
    float v = g_agg[idx] * g_scale[c] + g_shift[c];
    out[idx] = fmaxf(v, 0.0f);
}

// ---------------- launch ----------------
extern "C" void kernel_launch(void* const* d_in, const int* in_sizes, int n_in,
                              void* d_out, int out_size) {
    const float* x = (const float*)d_in[0];
    const void* ei = d_in[1];
    const float* W[3]  = {(const float*)d_in[2],  (const float*)d_in[6],  (const float*)d_in[10]};
    const float* bb[3] = {(const float*)d_in[3],  (const float*)d_in[7],  (const float*)d_in[11]};
    const float* gg[3] = {(const float*)d_in[4],  (const float*)d_in[8],  (const float*)d_in[12]};
    const float* be[3] = {(const float*)d_in[5],  (const float*)d_in[9],  (const float*)d_in[13]};
    float* out = (float*)d_out;

    const int eblocks = (N_EDGES + 255) / 256;
    const int gemm_blocks = (N_NODES + 63) / 64;
    const int agg_blocks = (N_NODES + 7) / 8;
    const int stats_blocks = (N_NODES + 127) / 128;
    const int app_blocks = (N_NODES * D + 255) / 256;

    detect_kernel<<<eblocks, 256>>>((const int*)ei);            // 1
    convert_count_kernel<<<eblocks, 256>>>(ei);                 // 2
    scan_final_kernel<<<1, 1024>>>();                           // 3
    gemm_kernel<<<gemm_blocks, 256>>>(x, W[0], 0);              // 4 <- ncu slot
    fill_kernel<<<eblocks, 256>>>();                            // 5

    for (int layer = 0; layer < 3; layer++) {
        if (layer > 0)
            gemm_kernel<<<gemm_blocks, 256>>>(x, W[layer], 1);
        aggregate_kernel<<<agg_blocks, 256>>>(bb[layer]);
        stats_kernel<<<stats_blocks, 128>>>();
        bn_final_kernel<<<1, D>>>(gg[layer], be[layer]);
    }
    apply_kernel<<<app_blocks, 256>>>(out);
}

// round 10
// speedup vs baseline: 3.1337x; 1.1949x over previous
#include <cuda_runtime.h>
#include <cuda_fp16.h>
#include <math.h>

#define N_NODES 50000
#define N_EDGES 1600000
#define D 128
#define BN_EPS 1e-5f
#define NB 196   // scan blocks: 196*256 = 50176 >= N_NODES

// ---------------- device scratch (no allocations allowed) ----------------
__device__ __align__(16) float  g_hws[N_NODES * D];   // (h @ W) * dinv[row], fp32
__device__ __align__(16) __half g_hws_h[N_NODES * D]; // same, fp16 (gather copy)
__device__ __align__(16) float  g_agg[N_NODES * D];   // pre-BN activations
__device__ int   g_src[N_EDGES];
__device__ int   g_dst[N_EDGES];
__device__ int   g_is_i32 = 0;                        // set-only dtype flag
__device__ int   g_deg[N_NODES];
__device__ int   g_rowstart[N_NODES + 1];
__device__ int   g_cursor[N_NODES];
__device__ int   g_csr_src[N_EDGES];
__device__ int   g_blocksum[NB];
__device__ int   g_blockoff[NB];
__device__ float g_dinv[N_NODES];                     // rsqrt(deg+2)
__device__ float g_colsum[D];
__device__ float g_colsq[D];
__device__ float g_scale[D];
__device__ float g_shift[D];

// ---------------- input canonicalization + degree zero ----------------
__global__ void detect_kernel(const int* __restrict__ p32) {
    int i = blockIdx.x * blockDim.x + threadIdx.x;
    if (i < N_NODES) g_deg[i] = 0;
    if (i < 8192 && p32[2 * i + 1] != 0) g_is_i32 = 1;
}

__global__ void convert_count_kernel(const void* __restrict__ eiv) {
    int e = blockIdx.x * blockDim.x + threadIdx.x;
    if (e >= N_EDGES) return;
    int s, d;
    if (g_is_i32) {
        const int* p = (const int*)eiv;
        s = p[e]; d = p[N_EDGES + e];
    } else {
        const long long* p = (const long long*)eiv;
        s = (int)p[e]; d = (int)p[N_EDGES + e];
    }
    g_src[e] = s;
    g_dst[e] = d;
    atomicAdd(&g_deg[d], 1);
}

// ---- grid scan: A) block-local exclusive scan + dinv, B) block offsets,
//                 C) fixup + cursor ----
__global__ void scanA_kernel() {
    __shared__ int wsum[8];
    const int tid = threadIdx.x, lane = tid & 31, w = tid >> 5;
    const int i = blockIdx.x * 256 + tid;
    int v = (i < N_NODES) ? g_deg[i] : 0;
    int x = v;
#pragma unroll
    for (int off = 1; off < 32; off <<= 1) {
        int n = __shfl_up_sync(0xffffffffu, x, off);
        if (lane >= off) x += n;
    }
    if (lane == 31) wsum[w] = x;
    __syncthreads();
    if (w == 0) {
        int t = (lane < 8) ? wsum[lane] : 0;
#pragma unroll
        for (int off = 1; off < 8; off <<= 1) {
            int n = __shfl_up_sync(0xffffffffu, t, off);
            if (lane >= off) t += n;
        }
        if (lane < 8) wsum[lane] = t;
    }
    __syncthreads();
    int wpre = (w == 0) ? 0 : wsum[w - 1];
    if (i < N_NODES) {
        g_rowstart[i] = x - v + wpre;          // block-local exclusive
        g_dinv[i] = rsqrtf((float)v + 2.0f);
    }
    if (tid == 255) g_blocksum[blockIdx.x] = x + wpre;  // block total
}

__global__ void scanB_kernel() {
    __shared__ int wsum[8];
    const int tid = threadIdx.x, lane = tid & 31, w = tid >> 5;
    int v = (tid < NB) ? g_blocksum[tid] : 0;
    int x = v;
#pragma unroll
    for (int off = 1; off < 32; off <<= 1) {
        int n = __shfl_up_sync(0xffffffffu, x, off);
        if (lane >= off) x += n;
    }
    if (lane == 31) wsum[w] = x;
    __syncthreads();
    if (w == 0) {
        int t = (lane < 8) ? wsum[lane] : 0;
#pragma unroll
        for (int off = 1; off < 8; off <<= 1) {
            int n = __shfl_up_sync(0xffffffffu, t, off);
            if (lane >= off) t += n;
        }
        if (lane < 8) wsum[lane] = t;
    }
    __syncthreads();
    int wpre = (w == 0) ? 0 : wsum[w - 1];
    if (tid < NB) g_blockoff[tid] = x - v + wpre;
    if (tid == 255) g_rowstart[N_NODES] = x + wpre;   // total edges
}

__global__ void scanC_kernel() {
    int i = blockIdx.x * 256 + threadIdx.x;
    if (i < N_NODES) {
        int rs = g_rowstart[i] + g_blockoff[blockIdx.x];
        g_rowstart[i] = rs;
        g_cursor[i] = rs;
    }
}

__global__ void fill_kernel() {
    int e = blockIdx.x * blockDim.x + threadIdx.x;
    if (e < N_EDGES) {
        int p = atomicAdd(&g_cursor[g_dst[e]], 1);
        g_csr_src[p] = g_src[e];
    }
}

// ---------------- double-buffered register-tiled GEMM -----------------------
// tile: 64 rows x 128 cols, 256 threads, 4x8 micro-tile, K sliced 8 deep,
// 2-stage smem pipeline (LDG of slice s+1 overlaps compute of slice s).
// mode 0: input = A (x). mode 1: input = ReLU(g_agg*scale+shift).
__global__ void __launch_bounds__(256) gemm_kernel(const float* __restrict__ A,
                                                   const float* __restrict__ W,
                                                   int mode) {
    __shared__ float sA[2][8][68];
    __shared__ float sW[2][8][132];
    __shared__ float s_scale[D], s_shift[D];

    const int tid = threadIdx.x;
    const int rb = blockIdx.x * 64;
    const int tx = tid & 15;          // cols tx*4, 64+tx*4
    const int ty = tid >> 4;          // rows ty*4..ty*4+3

    if (mode && tid < D) { s_scale[tid] = g_scale[tid]; s_shift[tid] = g_shift[tid]; }
    if (blockIdx.x == 0 && tid < D) { g_colsum[tid] = 0.0f; g_colsq[tid] = 0.0f; }
    __syncthreads();   // s_scale/s_shift visible before any staging read

    float c[4][8];
#pragma unroll
    for (int i = 0; i < 4; i++)
#pragma unroll
        for (int j = 0; j < 8; j++) c[i][j] = 0.0f;

    // staging roles
    const int a_row = tid >> 1;            // tid<128: rows 0..63
    const int a_k4 = (tid & 1) * 4;        // k offset 0 or 4
    const int w_k = tid >> 5;              // 0..7
    const int w_c4 = (tid & 31) * 4;       // col 0..124
    const int grow = rb + a_row;
    const float* __restrict__ srcA = mode ? g_agg : A;

    float4 aReg = make_float4(0.f, 0.f, 0.f, 0.f);
    float4 wReg;

    // prologue: load slice 0
    if (tid < 128 && grow < N_NODES) {
        aReg = *(const float4*)&srcA[grow * D + a_k4];
        if (mode) {
            aReg.x = fmaxf(aReg.x * s_scale[a_k4 + 0] + s_shift[a_k4 + 0], 0.f);
            aReg.y = fmaxf(aReg.y * s_scale[a_k4 + 1] + s_shift[a_k4 + 1], 0.f);
            aReg.z = fmaxf(aReg.z * s_scale[a_k4 + 2] + s_shift[a_k4 + 2], 0.f);
            aReg.w = fmaxf(aReg.w * s_scale[a_k4 + 3] + s_shift[a_k4 + 3], 0.f);
        }
    }
    wReg = *(const float4*)&W[w_k * D + w_c4];
    if (tid < 128) {
        sA[0][a_k4 + 0][a_row] = aReg.x;
        sA[0][a_k4 + 1][a_row] = aReg.y;
        sA[0][a_k4 + 2][a_row] = aReg.z;
        sA[0][a_k4 + 3][a_row] = aReg.w;
    }
    *(float4*)&sW[0][w_k][w_c4] = wReg;
    __syncthreads();

#pragma unroll 2
    for (int s = 0; s < 16; s++) {
        const int cur = s & 1;
        const int kk_next = (s + 1) * 8;

        // issue next-slice loads (latency hidden by compute below)
        if (s < 15) {
            aReg = make_float4(0.f, 0.f, 0.f, 0.f);
            if (tid < 128 && grow < N_NODES) {
                aReg = *(const float4*)&srcA[grow * D + kk_next + a_k4];
                if (mode) {
                    int cb = kk_next + a_k4;
                    aReg.x = fmaxf(aReg.x * s_scale[cb + 0] + s_shift[cb + 0], 0.f);
                    aReg.y = fmaxf(aReg.y * s_scale[cb + 1] + s_shift[cb + 1], 0.f);
                    aReg.z = fmaxf(aReg.z * s_scale[cb + 2] + s_shift[cb + 2], 0.f);
                    aReg.w = fmaxf(aReg.w * s_scale[cb + 3] + s_shift[cb + 3], 0.f);
                }
            }
            wReg = *(const float4*)&W[(kk_next + w_k) * D + w_c4];
        }

        // compute on current buffer
#pragma unroll
        for (int k = 0; k < 8; k++) {
            float4 a0 = *(const float4*)&sA[cur][k][ty * 4];
            float4 b0 = *(const float4*)&sW[cur][k][tx * 4];
            float4 b1 = *(const float4*)&sW[cur][k][64 + tx * 4];
            float av[4] = {a0.x, a0.y, a0.z, a0.w};
            float bv[8] = {b0.x, b0.y, b0.z, b0.w, b1.x, b1.y, b1.z, b1.w};
#pragma unroll
            for (int i = 0; i < 4; i++)
#pragma unroll
                for (int j = 0; j < 8; j++) c[i][j] += av[i] * bv[j];
        }

        // store next slice into alternate buffer
        if (s < 15) {
            const int nxt = cur ^ 1;
            if (tid < 128) {
                sA[nxt][a_k4 + 0][a_row] = aReg.x;
                sA[nxt][a_k4 + 1][a_row] = aReg.y;
                sA[nxt][a_k4 + 2][a_row] = aReg.z;
                sA[nxt][a_k4 + 3][a_row] = aReg.w;
            }
            *(float4*)&sW[nxt][w_k][w_c4] = wReg;
            __syncthreads();
        }
    }

    // ---- epilogue: fp32 hws + packed fp16 copy ----
    __half2* hout = reinterpret_cast<__half2*>(g_hws_h);
#pragma unroll
    for (int i = 0; i < 4; i++) {
        int row = rb + ty * 4 + i;
        if (row >= N_NODES) break;
        float di = g_dinv[row];
        float4 lo = make_float4(c[i][0] * di, c[i][1] * di, c[i][2] * di, c[i][3] * di);
        float4 hi = make_float4(c[i][4] * di, c[i][5] * di, c[i][6] * di, c[i][7] * di);
        *(float4*)&g_hws[row * D + tx * 4] = lo;
        *(float4*)&g_hws[row * D + 64 + tx * 4] = hi;
        int hb = row * (D / 2);
        hout[hb + tx * 2]     = __floats2half2_rn(lo.x, lo.y);
        hout[hb + tx * 2 + 1] = __floats2half2_rn(lo.z, lo.w);
        hout[hb + 32 + tx * 2]     = __floats2half2_rn(hi.x, hi.y);
        hout[hb + 32 + tx * 2 + 1] = __floats2half2_rn(hi.z, hi.w);
    }
}

// ---------------- aggregate (warp per node, fp16 gathers) -------------------
__global__ void aggregate_kernel(const float* __restrict__ b) {
    const int node = blockIdx.x * 8 + (threadIdx.x >> 5);
    const int lane = threadIdx.x & 31;
    if (node >= N_NODES) return;

    const int beg = g_rowstart[node];
    const int end = g_rowstart[node + 1];
    const uint2* __restrict__ hh = reinterpret_cast<const uint2*>(g_hws_h);

    float4 acc = make_float4(0.0f, 0.0f, 0.0f, 0.0f);
    for (int k0 = beg; k0 < end; k0 += 32) {
        int t = k0 + lane;
        int idx = (t < end) ? g_csr_src[t] : 0;
        int m = min(32, end - k0);
#pragma unroll 8
        for (int j = 0; j < m; j++) {
            int s = __shfl_sync(0xffffffffu, idx, j);
            uint2 raw = hh[s * 32 + lane];
            float2 f0 = __half22float2(*reinterpret_cast<__half2*>(&raw.x));
            float2 f1 = __half22float2(*reinterpret_cast<__half2*>(&raw.y));
            acc.x += f0.x; acc.y += f0.y; acc.z += f1.x; acc.w += f1.y;
        }
    }

    const float4* __restrict__ hws4 = reinterpret_cast<const float4*>(g_hws);
    float4 self = hws4[node * 32 + lane];
    float dinv = g_dinv[node];
    float4 b4 = reinterpret_cast<const float4*>(b)[lane];
    float4 o;
    o.x = dinv * (acc.x + 2.0f * self.x) + b4.x;
    o.y = dinv * (acc.y + 2.0f * self.y) + b4.y;
    o.z = dinv * (acc.z + 2.0f * self.z) + b4.z;
    o.w = dinv * (acc.w + 2.0f * self.w) + b4.w;
    reinterpret_cast<float4*>(g_agg)[node * 32 + lane] = o;
}

// column sums/sumsq over g_agg; block handles 128 rows (thread = column)
__global__ void stats_kernel() {
    const int c = threadIdx.x;
    const int r0 = blockIdx.x * 128;
    float s = 0.0f, sq = 0.0f;
    for (int i = 0; i < 128; i++) {
        int r = r0 + i;
        if (r >= N_NODES) break;
        float v = g_agg[r * D + c];
        s += v;
        sq += v * v;
    }
    atomicAdd(&g_colsum[c], s);
    atomicAdd(&g_colsq[c], sq);
}

__global__ void bn_final_kernel(const float* __restrict__ gamma,
                                const float* __restrict__ beta) {
    int c = threadIdx.x;
    float mean = g_colsum[c] * (1.0f / (float)N_NODES);
    float var = g_colsq[c] * (1.0f / (float)N_NODES) - mean * mean;
    float sc = gamma[c] * rsqrtf(var + BN_EPS);
    g_scale[c] = sc;
    g_shift[c] = beta[c] - mean * sc;
}

// final layer only: out = relu(agg*scale + shift)
__global__ void apply_kernel(float* __restrict__ out) {
    int idx = blockIdx.x * blockDim.x + threadIdx.x;
    if (idx >= N_NODES * D) return;
    int c = idx & (D - 1);
    float v = g_agg[idx] * g_scale[c] + g_shift[c];
    out[idx] = fmaxf(v, 0.0f);
}

// ---------------- launch ----------------
extern "C" void kernel_launch(void* const* d_in, const int* in_sizes, int n_in,
                              void* d_out, int out_size) {
    const float* x = (const float*)d_in[0];
    const void* ei = d_in[1];
    const float* W[3]  = {(const float*)d_in[2],  (const float*)d_in[6],  (const float*)d_in[10]};
    const float* bb[3] = {(const float*)d_in[3],  (const float*)d_in[7],  (const float*)d_in[11]};
    const float* gg[3] = {(const float*)d_in[4],  (const float*)d_in[8],  (const float*)d_in[12]};
    const float* be[3] = {(const float*)d_in[5],  (const float*)d_in[9],  (const float*)d_in[13]};
    float* out = (float*)d_out;

    const int eblocks = (N_EDGES + 255) / 256;
    const int gemm_blocks = (N_NODES + 63) / 64;
    const int agg_blocks = (N_NODES + 7) / 8;
    const int stats_blocks = (N_NODES + 127) / 128;
    const int app_blocks = (N_NODES * D + 255) / 256;

    detect_kernel<<<NB, 256>>>((const int*)ei);                 // 1
    convert_count_kernel<<<eblocks, 256>>>(ei);                 // 2
    scanA_kernel<<<NB, 256>>>();                                // 3 (writes dinv)
    gemm_kernel<<<gemm_blocks, 256>>>(x, W[0], 0);              // 4 <- ncu slot
    scanB_kernel<<<1, 256>>>();                                 // 5
    scanC_kernel<<<NB, 256>>>();                                // 6
    fill_kernel<<<eblocks, 256>>>();                            // 7

    for (int layer = 0; layer < 3; layer++) {
        if (layer > 0)
            gemm_kernel<<<gemm_blocks, 256>>>(x, W[layer], 1);
        aggregate_kernel<<<agg_blocks, 256>>>(bb[layer]);
        stats_kernel<<<stats_blocks, 128>>>();
        bn_final_kernel<<<1, D>>>(gg[layer], be[layer]);
    }
    apply_kernel<<<app_blocks, 256>>>(out);
}

// round 11
// speedup vs baseline: 3.3044x; 1.0545x over previous
#include <cuda_runtime.h>
#include <cuda_fp16.h>
#include <math.h>

#define N_NODES 50000
#define N_EDGES 1600000
#define D 128
#define BN_EPS 1e-5f
#define NB 196   // scan blocks: 196*256 = 50176 >= N_NODES

// ---------------- device scratch (no allocations allowed) ----------------
__device__ __align__(16) float  g_hws[N_NODES * D];   // (h @ W) * dinv[row], fp32
__device__ __align__(16) __half g_hws_h[N_NODES * D]; // same, fp16 (gather copy)
__device__ __align__(16) float  g_agg[N_NODES * D];   // pre-BN activations
__device__ int   g_src[N_EDGES];
__device__ int   g_dst[N_EDGES];
__device__ int   g_is_i32 = 0;                        // set-only dtype flag
__device__ int   g_deg[N_NODES];
__device__ int   g_rowstart[N_NODES + 1];
__device__ int   g_cursor[N_NODES];
__device__ int   g_csr_src[N_EDGES];
__device__ int   g_blocksum[NB];
__device__ int   g_blockoff[NB];
__device__ float g_dinv[N_NODES];                     // rsqrt(deg+2)
__device__ float g_colsum[D];
__device__ float g_colsq[D];
__device__ float g_scale[D];
__device__ float g_shift[D];

// ---------------- tf32 helpers (fragment layout verified in R6) ------------
__device__ __forceinline__ unsigned f2tf32(float x) {
    unsigned r;
    asm("cvt.rna.tf32.f32 %0, %1;" : "=r"(r) : "f"(x));
    return r;
}
__device__ __forceinline__ void mma_tf32(float c[4], const unsigned a[4],
                                         unsigned b0, unsigned b1) {
    asm volatile(
        "mma.sync.aligned.m16n8k8.row.col.f32.tf32.tf32.f32 "
        "{%0,%1,%2,%3}, {%4,%5,%6,%7}, {%8,%9}, {%0,%1,%2,%3};"
        : "+f"(c[0]), "+f"(c[1]), "+f"(c[2]), "+f"(c[3])
        : "r"(a[0]), "r"(a[1]), "r"(a[2]), "r"(a[3]), "r"(b0), "r"(b1));
}

// ---------------- input canonicalization + degree zero ----------------
__global__ void detect_kernel(const int* __restrict__ p32) {
    int i = blockIdx.x * blockDim.x + threadIdx.x;
    if (i < N_NODES) g_deg[i] = 0;
    if (i < 8192 && p32[2 * i + 1] != 0) g_is_i32 = 1;
}

__global__ void convert_count_kernel(const void* __restrict__ eiv) {
    int e = blockIdx.x * blockDim.x + threadIdx.x;
    if (e >= N_EDGES) return;
    int s, d;
    if (g_is_i32) {
        const int* p = (const int*)eiv;
        s = p[e]; d = p[N_EDGES + e];
    } else {
        const long long* p = (const long long*)eiv;
        s = (int)p[e]; d = (int)p[N_EDGES + e];
    }
    g_src[e] = s;
    g_dst[e] = d;
    atomicAdd(&g_deg[d], 1);
}

// ---- grid scan ----
__global__ void scanA_kernel() {
    __shared__ int wsum[8];
    const int tid = threadIdx.x, lane = tid & 31, w = tid >> 5;
    const int i = blockIdx.x * 256 + tid;
    int v = (i < N_NODES) ? g_deg[i] : 0;
    int x = v;
#pragma unroll
    for (int off = 1; off < 32; off <<= 1) {
        int n = __shfl_up_sync(0xffffffffu, x, off);
        if (lane >= off) x += n;
    }
    if (lane == 31) wsum[w] = x;
    __syncthreads();
    if (w == 0) {
        int t = (lane < 8) ? wsum[lane] : 0;
#pragma unroll
        for (int off = 1; off < 8; off <<= 1) {
            int n = __shfl_up_sync(0xffffffffu, t, off);
            if (lane >= off) t += n;
        }
        if (lane < 8) wsum[lane] = t;
    }
    __syncthreads();
    int wpre = (w == 0) ? 0 : wsum[w - 1];
    if (i < N_NODES) {
        g_rowstart[i] = x - v + wpre;
        g_dinv[i] = rsqrtf((float)v + 2.0f);
    }
    if (tid == 255) g_blocksum[blockIdx.x] = x + wpre;
}

__global__ void scanB_kernel() {
    __shared__ int wsum[8];
    const int tid = threadIdx.x, lane = tid & 31, w = tid >> 5;
    int v = (tid < NB) ? g_blocksum[tid] : 0;
    int x = v;
#pragma unroll
    for (int off = 1; off < 32; off <<= 1) {
        int n = __shfl_up_sync(0xffffffffu, x, off);
        if (lane >= off) x += n;
    }
    if (lane == 31) wsum[w] = x;
    __syncthreads();
    if (w == 0) {
        int t = (lane < 8) ? wsum[lane] : 0;
#pragma unroll
        for (int off = 1; off < 8; off <<= 1) {
            int n = __shfl_up_sync(0xffffffffu, t, off);
            if (lane >= off) t += n;
        }
        if (lane < 8) wsum[lane] = t;
    }
    __syncthreads();
    int wpre = (w == 0) ? 0 : wsum[w - 1];
    if (tid < NB) g_blockoff[tid] = x - v + wpre;
    if (tid == 255) g_rowstart[N_NODES] = x + wpre;
}

__global__ void scanC_kernel() {
    int i = blockIdx.x * 256 + threadIdx.x;
    if (i < N_NODES) {
        int rs = g_rowstart[i] + g_blockoff[blockIdx.x];
        g_rowstart[i] = rs;
        g_cursor[i] = rs;
    }
}

__global__ void fill_kernel() {
    int e = blockIdx.x * blockDim.x + threadIdx.x;
    if (e < N_EDGES) {
        int p = atomicAdd(&g_cursor[g_dst[e]], 1);
        g_csr_src[p] = g_src[e];
    }
}

// ---------------- split-tf32 tensor GEMM ------------------------------------
// Tile 64 rows x 128 cols, 256 threads = 8 warps: warp w -> row group rg=w&3
// (rows rg*16..+15), col group cg=w>>2 (cols cg*64..+63). K sliced 16-deep.
// 3xTF32: hi*hi + hi*lo + lo*hi. Fragment maps identical to R6 (verified).
// mode 0: input = A. mode 1: input = ReLU(g_agg*scale+shift).
__global__ void __launch_bounds__(256) gemm_kernel(const float* __restrict__ A,
                                                   const float* __restrict__ W,
                                                   int mode) {
    __shared__ float sAh[64][20], sAl[64][20];    // row-major, pad 20 (20g+t unique mod 32)
    __shared__ float sWh[16][136], sWl[16][136];  // k-major, pad 136 (8t+g unique mod 32)
    __shared__ float s_scale[D], s_shift[D];

    const int tid = threadIdx.x;
    const int rb = blockIdx.x * 64;
    const int lane = tid & 31, w = tid >> 5;
    const int rg = w & 3, cg = w >> 2;
    const int gi = lane >> 2, t4 = lane & 3;

    if (mode && tid < D) { s_scale[tid] = g_scale[tid]; s_shift[tid] = g_shift[tid]; }
    if (blockIdx.x == 0 && tid < D) { g_colsum[tid] = 0.0f; g_colsq[tid] = 0.0f; }
    __syncthreads();   // s_scale/s_shift visible before any staging read

    float c[8][4];
#pragma unroll
    for (int n0 = 0; n0 < 8; n0++)
#pragma unroll
        for (int j = 0; j < 4; j++) c[n0][j] = 0.0f;

    // staging roles: A -> thread t loads float4 at (row=t>>2, k=(t&3)*4)
    const int a_row = tid >> 2;          // 0..63
    const int a_kp = (tid & 3) * 4;      // 0,4,8,12
    const int grow = rb + a_row;
    const float* __restrict__ srcA = mode ? g_agg : A;

    for (int kk = 0; kk < D; kk += 16) {
        // ---- stage A (64 x 16), split hi/lo ----
        {
            float4 a = make_float4(0.f, 0.f, 0.f, 0.f);
            if (grow < N_NODES) {
                a = *(const float4*)&srcA[grow * D + kk + a_kp];
                if (mode) {
                    int cb = kk + a_kp;
                    a.x = fmaxf(a.x * s_scale[cb + 0] + s_shift[cb + 0], 0.f);
                    a.y = fmaxf(a.y * s_scale[cb + 1] + s_shift[cb + 1], 0.f);
                    a.z = fmaxf(a.z * s_scale[cb + 2] + s_shift[cb + 2], 0.f);
                    a.w = fmaxf(a.w * s_scale[cb + 3] + s_shift[cb + 3], 0.f);
                }
            }
            float hx = __uint_as_float(f2tf32(a.x));
            float hy = __uint_as_float(f2tf32(a.y));
            float hz = __uint_as_float(f2tf32(a.z));
            float hw = __uint_as_float(f2tf32(a.w));
            *(float4*)&sAh[a_row][a_kp] = make_float4(hx, hy, hz, hw);
            *(float4*)&sAl[a_row][a_kp] = make_float4(
                __uint_as_float(f2tf32(a.x - hx)), __uint_as_float(f2tf32(a.y - hy)),
                __uint_as_float(f2tf32(a.z - hz)), __uint_as_float(f2tf32(a.w - hw)));
        }
        // ---- stage W (16 x 128), split hi/lo ----
#pragma unroll
        for (int i = 0; i < 2; i++) {
            int idx = i * 256 + tid;
            int k = idx >> 5;
            int c4 = (idx & 31) * 4;
            float4 b = *(const float4*)&W[(kk + k) * D + c4];
            float hx = __uint_as_float(f2tf32(b.x));
            float hy = __uint_as_float(f2tf32(b.y));
            float hz = __uint_as_float(f2tf32(b.z));
            float hw = __uint_as_float(f2tf32(b.w));
            *(float4*)&sWh[k][c4] = make_float4(hx, hy, hz, hw);
            *(float4*)&sWl[k][c4] = make_float4(
                __uint_as_float(f2tf32(b.x - hx)), __uint_as_float(f2tf32(b.y - hy)),
                __uint_as_float(f2tf32(b.z - hz)), __uint_as_float(f2tf32(b.w - hw)));
        }
        __syncthreads();

        // ---- compute: 2 k-steps of 8 ----
#pragma unroll
        for (int ks = 0; ks < 2; ks++) {
            const int k0 = ks * 8;
            const int r0 = rg * 16 + gi, r1 = r0 + 8;
            unsigned ah[4] = {__float_as_uint(sAh[r0][k0 + t4]),
                              __float_as_uint(sAh[r1][k0 + t4]),
                              __float_as_uint(sAh[r0][k0 + t4 + 4]),
                              __float_as_uint(sAh[r1][k0 + t4 + 4])};
            unsigned al[4] = {__float_as_uint(sAl[r0][k0 + t4]),
                              __float_as_uint(sAl[r1][k0 + t4]),
                              __float_as_uint(sAl[r0][k0 + t4 + 4]),
                              __float_as_uint(sAl[r1][k0 + t4 + 4])};
#pragma unroll
            for (int n0 = 0; n0 < 8; n0++) {
                int nb = cg * 64 + n0 * 8 + gi;
                unsigned b0h = __float_as_uint(sWh[k0 + t4][nb]);
                unsigned b1h = __float_as_uint(sWh[k0 + t4 + 4][nb]);
                unsigned b0l = __float_as_uint(sWl[k0 + t4][nb]);
                unsigned b1l = __float_as_uint(sWl[k0 + t4 + 4][nb]);
                mma_tf32(c[n0], ah, b0h, b1h);   // hi*hi
                mma_tf32(c[n0], ah, b0l, b1l);   // hi*lo
                mma_tf32(c[n0], al, b0h, b1h);   // lo*hi
            }
        }
        __syncthreads();
    }

    // ---- epilogue: c0=(r0,n) c1=(r0,n+1) c2=(r0+8,n) c3=(r0+8,n+1) ----
    const int row0 = rb + rg * 16 + gi;
    const int row1 = row0 + 8;
    const float di0 = (row0 < N_NODES) ? g_dinv[row0] : 0.0f;
    const float di1 = (row1 < N_NODES) ? g_dinv[row1] : 0.0f;
    __half2* hout = reinterpret_cast<__half2*>(g_hws_h);
#pragma unroll
    for (int n0 = 0; n0 < 8; n0++) {
        int n = cg * 64 + n0 * 8 + 2 * t4;
        int hc = n >> 1;  // half2 column index
        if (row0 < N_NODES) {
            float2 v = make_float2(c[n0][0] * di0, c[n0][1] * di0);
            *(float2*)&g_hws[row0 * D + n] = v;
            hout[row0 * (D / 2) + hc] = __floats2half2_rn(v.x, v.y);
        }
        if (row1 < N_NODES) {
            float2 v = make_float2(c[n0][2] * di1, c[n0][3] * di1);
            *(float2*)&g_hws[row1 * D + n] = v;
            hout[row1 * (D / 2) + hc] = __floats2half2_rn(v.x, v.y);
        }
    }
}

// ---------------- aggregate (warp per node, fp16 gathers) -------------------
__global__ void aggregate_kernel(const float* __restrict__ b) {
    const int node = blockIdx.x * 8 + (threadIdx.x >> 5);
    const int lane = threadIdx.x & 31;
    if (node >= N_NODES) return;

    const int beg = g_rowstart[node];
    const int end = g_rowstart[node + 1];
    const uint2* __restrict__ hh = reinterpret_cast<const uint2*>(g_hws_h);

    float4 acc = make_float4(0.0f, 0.0f, 0.0f, 0.0f);
    for (int k0 = beg; k0 < end; k0 += 32) {
        int t = k0 + lane;
        int idx = (t < end) ? g_csr_src[t] : 0;
        int m = min(32, end - k0);
#pragma unroll 8
        for (int j = 0; j < m; j++) {
            int s = __shfl_sync(0xffffffffu, idx, j);
            uint2 raw = hh[s * 32 + lane];
            float2 f0 = __half22float2(*reinterpret_cast<__half2*>(&raw.x));
            float2 f1 = __half22float2(*reinterpret_cast<__half2*>(&raw.y));
            acc.x += f0.x; acc.y += f0.y; acc.z += f1.x; acc.w += f1.y;
        }
    }

    const float4* __restrict__ hws4 = reinterpret_cast<const float4*>(g_hws);
    float4 self = hws4[node * 32 + lane];
    float dinv = g_dinv[node];
    float4 b4 = reinterpret_cast<const float4*>(b)[lane];
    float4 o;
    o.x = dinv * (acc.x + 2.0f * self.x) + b4.x;
    o.y = dinv * (acc.y + 2.0f * self.y) + b4.y;
    o.z = dinv * (acc.z + 2.0f * self.z) + b4.z;
    o.w = dinv * (acc.w + 2.0f * self.w) + b4.w;
    reinterpret_cast<float4*>(g_agg)[node * 32 + lane] = o;
}

// column sums/sumsq over g_agg; block handles 128 rows (thread = column)
__global__ void stats_kernel() {
    const int c = threadIdx.x;
    const int r0 = blockIdx.x * 128;
    float s = 0.0f, sq = 0.0f;
    for (int i = 0; i < 128; i++) {
        int r = r0 + i;
        if (r >= N_NODES) break;
        float v = g_agg[r * D + c];
        s += v;
        sq += v * v;
    }
    atomicAdd(&g_colsum[c], s);
    atomicAdd(&g_colsq[c], sq);
}

__global__ void bn_final_kernel(const float* __restrict__ gamma,
                                const float* __restrict__ beta) {
    int c = threadIdx.x;
    float mean = g_colsum[c] * (1.0f / (float)N_NODES);
    float var = g_colsq[c] * (1.0f / (float)N_NODES) - mean * mean;
    float sc = gamma[c] * rsqrtf(var + BN_EPS);
    g_scale[c] = sc;
    g_shift[c] = beta[c] - mean * sc;
}

// final layer only: out = relu(agg*scale + shift)
__global__ void apply_kernel(float* __restrict__ out) {
    int idx = blockIdx.x * blockDim.x + threadIdx.x;
    if (idx >= N_NODES * D) return;
    int c = idx & (D - 1);
    float v = g_agg[idx] * g_scale[c] + g_shift[c];
    out[idx] = fmaxf(v, 0.0f);
}

// ---------------- launch ----------------
extern "C" void kernel_launch(void* const* d_in, const int* in_sizes, int n_in,
                              void* d_out, int out_size) {
    const float* x = (const float*)d_in[0];
    const void* ei = d_in[1];
    const float* W[3]  = {(const float*)d_in[2],  (const float*)d_in[6],  (const float*)d_in[10]};
    const float* bb[3] = {(const float*)d_in[3],  (const float*)d_in[7],  (const float*)d_in[11]};
    const float* gg[3] = {(const float*)d_in[4],  (const float*)d_in[8],  (const float*)d_in[12]};
    const float* be[3] = {(const float*)d_in[5],  (const float*)d_in[9],  (const float*)d_in[13]};
    float* out = (float*)d_out;

    const int eblocks = (N_EDGES + 255) / 256;
    const int gemm_blocks = (N_NODES + 63) / 64;
    const int agg_blocks = (N_NODES + 7) / 8;
    const int stats_blocks = (N_NODES + 127) / 128;
    const int app_blocks = (N_NODES * D + 255) / 256;

    detect_kernel<<<NB, 256>>>((const int*)ei);                 // 1
    convert_count_kernel<<<eblocks, 256>>>(ei);                 // 2
    scanA_kernel<<<NB, 256>>>();                                // 3 (writes dinv)
    gemm_kernel<<<gemm_blocks, 256>>>(x, W[0], 0);              // 4 <- ncu slot
    scanB_kernel<<<1, 256>>>();                                 // 5
    scanC_kernel<<<NB, 256>>>();                                // 6
    fill_kernel<<<eblocks, 256>>>();                            // 7

    for (int layer = 0; layer < 3; layer++) {
        if (layer > 0)
            gemm_kernel<<<gemm_blocks, 256>>>(x, W[layer], 1);
        aggregate_kernel<<<agg_blocks, 256>>>(bb[layer]);
        stats_kernel<<<stats_blocks, 128>>>();
        bn_final_kernel<<<1, D>>>(gg[layer], be[layer]);
    }
    apply_kernel<<<app_blocks, 256>>>(out);
}

// round 12
// speedup vs baseline: 3.3361x; 1.0096x over previous
#include <cuda_runtime.h>
#include <cuda_fp16.h>
#include <math.h>

#define N_NODES 50000
#define N_EDGES 1600000
#define D 128
#define BN_EPS 1e-5f
#define NB 196   // scan blocks: 196*256 = 50176 >= N_NODES

// ---------------- device scratch (no allocations allowed) ----------------
__device__ __align__(16) float  g_hws[N_NODES * D];   // (h @ W) * dinv[row], fp32
__device__ __align__(16) __half g_hws_h[N_NODES * D]; // same, fp16 (gather copy)
__device__ __align__(16) float  g_agg[N_NODES * D];   // pre-BN activations
__device__ int   g_src[N_EDGES];
__device__ int   g_dst[N_EDGES];
__device__ int   g_is_i32 = 0;                        // set-only dtype flag
__device__ int   g_deg[N_NODES];
__device__ int   g_rowstart[N_NODES + 1];
__device__ int   g_cursor[N_NODES];
__device__ int   g_csr_src[N_EDGES];
__device__ int   g_blocksum[NB];
__device__ int   g_blockoff[NB];
__device__ float g_dinv[N_NODES];                     // rsqrt(deg+2)
__device__ float g_colsum[D];
__device__ float g_colsq[D];
__device__ float g_scale[D];
__device__ float g_shift[D];

// ---------------- tf32 helpers (fragment layout verified in R6/R11) --------
__device__ __forceinline__ unsigned f2tf32(float x) {
    unsigned r;
    asm("cvt.rna.tf32.f32 %0, %1;" : "=r"(r) : "f"(x));
    return r;
}
__device__ __forceinline__ void mma_tf32(float c[4], const unsigned a[4],
                                         unsigned b0, unsigned b1) {
    asm volatile(
        "mma.sync.aligned.m16n8k8.row.col.f32.tf32.tf32.f32 "
        "{%0,%1,%2,%3}, {%4,%5,%6,%7}, {%8,%9}, {%0,%1,%2,%3};"
        : "+f"(c[0]), "+f"(c[1]), "+f"(c[2]), "+f"(c[3])
        : "r"(a[0]), "r"(a[1]), "r"(a[2]), "r"(a[3]), "r"(b0), "r"(b1));
}

// ---------------- input canonicalization + degree zero ----------------
__global__ void detect_kernel(const int* __restrict__ p32) {
    int i = blockIdx.x * blockDim.x + threadIdx.x;
    if (i < N_NODES) g_deg[i] = 0;
    if (i < 8192 && p32[2 * i + 1] != 0) g_is_i32 = 1;
}

__global__ void convert_count_kernel(const void* __restrict__ eiv) {
    int e = blockIdx.x * blockDim.x + threadIdx.x;
    if (e >= N_EDGES) return;
    int s, d;
    if (g_is_i32) {
        const int* p = (const int*)eiv;
        s = p[e]; d = p[N_EDGES + e];
    } else {
        const long long* p = (const long long*)eiv;
        s = (int)p[e]; d = (int)p[N_EDGES + e];
    }
    g_src[e] = s;
    g_dst[e] = d;
    atomicAdd(&g_deg[d], 1);
}

// ---- grid scan ----
__global__ void scanA_kernel() {
    __shared__ int wsum[8];
    const int tid = threadIdx.x, lane = tid & 31, w = tid >> 5;
    const int i = blockIdx.x * 256 + tid;
    int v = (i < N_NODES) ? g_deg[i] : 0;
    int x = v;
#pragma unroll
    for (int off = 1; off < 32; off <<= 1) {
        int n = __shfl_up_sync(0xffffffffu, x, off);
        if (lane >= off) x += n;
    }
    if (lane == 31) wsum[w] = x;
    __syncthreads();
    if (w == 0) {
        int t = (lane < 8) ? wsum[lane] : 0;
#pragma unroll
        for (int off = 1; off < 8; off <<= 1) {
            int n = __shfl_up_sync(0xffffffffu, t, off);
            if (lane >= off) t += n;
        }
        if (lane < 8) wsum[lane] = t;
    }
    __syncthreads();
    int wpre = (w == 0) ? 0 : wsum[w - 1];
    if (i < N_NODES) {
        g_rowstart[i] = x - v + wpre;
        g_dinv[i] = rsqrtf((float)v + 2.0f);
    }
    if (tid == 255) g_blocksum[blockIdx.x] = x + wpre;
}

__global__ void scanB_kernel() {
    __shared__ int wsum[8];
    const int tid = threadIdx.x, lane = tid & 31, w = tid >> 5;
    int v = (tid < NB) ? g_blocksum[tid] : 0;
    int x = v;
#pragma unroll
    for (int off = 1; off < 32; off <<= 1) {
        int n = __shfl_up_sync(0xffffffffu, x, off);
        if (lane >= off) x += n;
    }
    if (lane == 31) wsum[w] = x;
    __syncthreads();
    if (w == 0) {
        int t = (lane < 8) ? wsum[lane] : 0;
#pragma unroll
        for (int off = 1; off < 8; off <<= 1) {
            int n = __shfl_up_sync(0xffffffffu, t, off);
            if (lane >= off) t += n;
        }
        if (lane < 8) wsum[lane] = t;
    }
    __syncthreads();
    int wpre = (w == 0) ? 0 : wsum[w - 1];
    if (tid < NB) g_blockoff[tid] = x - v + wpre;
    if (tid == 255) g_rowstart[N_NODES] = x + wpre;
}

__global__ void scanC_kernel() {
    int i = blockIdx.x * 256 + threadIdx.x;
    if (i < N_NODES) {
        int rs = g_rowstart[i] + g_blockoff[blockIdx.x];
        g_rowstart[i] = rs;
        g_cursor[i] = rs;
    }
}

__global__ void fill_kernel() {
    int e = blockIdx.x * blockDim.x + threadIdx.x;
    if (e < N_EDGES) {
        int p = atomicAdd(&g_cursor[g_dst[e]], 1);
        g_csr_src[p] = g_src[e];
    }
}

// ---------------- split-tf32 tensor GEMM, double-buffered -------------------
// Tile 64 rows x 128 cols, 256 threads = 8 warps: warp w -> row group rg=w&3,
// col group cg=w>>2. K sliced 16-deep, 2-stage smem pipeline.
// 3xTF32: hi*hi + hi*lo + lo*hi. mode 1 fuses ReLU(agg*scale+shift).
__global__ void __launch_bounds__(256) gemm_kernel(const float* __restrict__ A,
                                                   const float* __restrict__ W,
                                                   int mode) {
    __shared__ float sAh[2][64][20], sAl[2][64][20];    // row-major, pad 20
    __shared__ float sWh[2][16][136], sWl[2][16][136];  // k-major, pad 136
    __shared__ float s_scale[D], s_shift[D];

    const int tid = threadIdx.x;
    const int rb = blockIdx.x * 64;
    const int lane = tid & 31, w = tid >> 5;
    const int rg = w & 3, cg = w >> 2;
    const int gi = lane >> 2, t4 = lane & 3;

    if (mode && tid < D) { s_scale[tid] = g_scale[tid]; s_shift[tid] = g_shift[tid]; }
    if (blockIdx.x == 0 && tid < D) { g_colsum[tid] = 0.0f; g_colsq[tid] = 0.0f; }
    __syncthreads();   // s_scale/s_shift visible before any staging read

    float c[8][4];
#pragma unroll
    for (int n0 = 0; n0 < 8; n0++)
#pragma unroll
        for (int j = 0; j < 4; j++) c[n0][j] = 0.0f;

    // staging roles
    const int a_row = tid >> 2;          // 0..63
    const int a_kp = (tid & 3) * 4;      // 0,4,8,12
    const int grow = rb + a_row;
    const int wk0 = tid >> 5;            // W load 0: k row 0..7
    const int wk1 = 8 + wk0;             //   load 1: k row 8..15
    const int wc4 = (tid & 31) * 4;      // W col 0..124
    const float* __restrict__ srcA = mode ? g_agg : A;

    float4 aReg, wReg0, wReg1;

    // helper lambdas (inlined by compiler)
    auto loadA = [&](int kk) {
        float4 a = make_float4(0.f, 0.f, 0.f, 0.f);
        if (grow < N_NODES) {
            a = *(const float4*)&srcA[grow * D + kk + a_kp];
            if (mode) {
                int cb = kk + a_kp;
                a.x = fmaxf(a.x * s_scale[cb + 0] + s_shift[cb + 0], 0.f);
                a.y = fmaxf(a.y * s_scale[cb + 1] + s_shift[cb + 1], 0.f);
                a.z = fmaxf(a.z * s_scale[cb + 2] + s_shift[cb + 2], 0.f);
                a.w = fmaxf(a.w * s_scale[cb + 3] + s_shift[cb + 3], 0.f);
            }
        }
        return a;
    };
    auto storeA = [&](int buf, float4 a) {
        float hx = __uint_as_float(f2tf32(a.x));
        float hy = __uint_as_float(f2tf32(a.y));
        float hz = __uint_as_float(f2tf32(a.z));
        float hw = __uint_as_float(f2tf32(a.w));
        *(float4*)&sAh[buf][a_row][a_kp] = make_float4(hx, hy, hz, hw);
        *(float4*)&sAl[buf][a_row][a_kp] = make_float4(
            __uint_as_float(f2tf32(a.x - hx)), __uint_as_float(f2tf32(a.y - hy)),
            __uint_as_float(f2tf32(a.z - hz)), __uint_as_float(f2tf32(a.w - hw)));
    };
    auto storeW = [&](int buf, int k, float4 b) {
        float hx = __uint_as_float(f2tf32(b.x));
        float hy = __uint_as_float(f2tf32(b.y));
        float hz = __uint_as_float(f2tf32(b.z));
        float hw = __uint_as_float(f2tf32(b.w));
        *(float4*)&sWh[buf][k][wc4] = make_float4(hx, hy, hz, hw);
        *(float4*)&sWl[buf][k][wc4] = make_float4(
            __uint_as_float(f2tf32(b.x - hx)), __uint_as_float(f2tf32(b.y - hy)),
            __uint_as_float(f2tf32(b.z - hz)), __uint_as_float(f2tf32(b.w - hw)));
    };

    // prologue: slice 0
    aReg  = loadA(0);
    wReg0 = *(const float4*)&W[wk0 * D + wc4];
    wReg1 = *(const float4*)&W[wk1 * D + wc4];
    storeA(0, aReg);
    storeW(0, wk0, wReg0);
    storeW(0, wk1, wReg1);
    __syncthreads();

    for (int s = 0; s < 8; s++) {
        const int cur = s & 1;
        const int kk_next = (s + 1) * 16;

        // prefetch next slice into registers (hidden under compute)
        if (s < 7) {
            aReg  = loadA(kk_next);
            wReg0 = *(const float4*)&W[(kk_next + wk0) * D + wc4];
            wReg1 = *(const float4*)&W[(kk_next + wk1) * D + wc4];
        }

        // ---- compute current buffer: 2 k-steps of 8 ----
#pragma unroll
        for (int ks = 0; ks < 2; ks++) {
            const int k0 = ks * 8;
            const int r0 = rg * 16 + gi, r1 = r0 + 8;
            unsigned ah[4] = {__float_as_uint(sAh[cur][r0][k0 + t4]),
                              __float_as_uint(sAh[cur][r1][k0 + t4]),
                              __float_as_uint(sAh[cur][r0][k0 + t4 + 4]),
                              __float_as_uint(sAh[cur][r1][k0 + t4 + 4])};
            unsigned al[4] = {__float_as_uint(sAl[cur][r0][k0 + t4]),
                              __float_as_uint(sAl[cur][r1][k0 + t4]),
                              __float_as_uint(sAl[cur][r0][k0 + t4 + 4]),
                              __float_as_uint(sAl[cur][r1][k0 + t4 + 4])};
#pragma unroll
            for (int n0 = 0; n0 < 8; n0++) {
                int nb = cg * 64 + n0 * 8 + gi;
                unsigned b0h = __float_as_uint(sWh[cur][k0 + t4][nb]);
                unsigned b1h = __float_as_uint(sWh[cur][k0 + t4 + 4][nb]);
                unsigned b0l = __float_as_uint(sWl[cur][k0 + t4][nb]);
                unsigned b1l = __float_as_uint(sWl[cur][k0 + t4 + 4][nb]);
                mma_tf32(c[n0], ah, b0h, b1h);   // hi*hi
                mma_tf32(c[n0], ah, b0l, b1l);   // hi*lo
                mma_tf32(c[n0], al, b0h, b1h);   // lo*hi
            }
        }

        // store next slice into alternate buffer
        if (s < 7) {
            const int nxt = cur ^ 1;
            storeA(nxt, aReg);
            storeW(nxt, wk0, wReg0);
            storeW(nxt, wk1, wReg1);
            __syncthreads();
        }
    }

    // ---- epilogue: c0=(r0,n) c1=(r0,n+1) c2=(r0+8,n) c3=(r0+8,n+1) ----
    const int row0 = rb + rg * 16 + gi;
    const int row1 = row0 + 8;
    const float di0 = (row0 < N_NODES) ? g_dinv[row0] : 0.0f;
    const float di1 = (row1 < N_NODES) ? g_dinv[row1] : 0.0f;
    __half2* hout = reinterpret_cast<__half2*>(g_hws_h);
#pragma unroll
    for (int n0 = 0; n0 < 8; n0++) {
        int n = cg * 64 + n0 * 8 + 2 * t4;
        int hc = n >> 1;
        if (row0 < N_NODES) {
            float2 v = make_float2(c[n0][0] * di0, c[n0][1] * di0);
            *(float2*)&g_hws[row0 * D + n] = v;
            hout[row0 * (D / 2) + hc] = __floats2half2_rn(v.x, v.y);
        }
        if (row1 < N_NODES) {
            float2 v = make_float2(c[n0][2] * di1, c[n0][3] * di1);
            *(float2*)&g_hws[row1 * D + n] = v;
            hout[row1 * (D / 2) + hc] = __floats2half2_rn(v.x, v.y);
        }
    }
}

// ---------------- aggregate (warp per node, fp16 gathers) -------------------
__global__ void aggregate_kernel(const float* __restrict__ b) {
    const int node = blockIdx.x * 8 + (threadIdx.x >> 5);
    const int lane = threadIdx.x & 31;
    if (node >= N_NODES) return;

    const int beg = g_rowstart[node];
    const int end = g_rowstart[node + 1];
    const uint2* __restrict__ hh = reinterpret_cast<const uint2*>(g_hws_h);

    float4 acc = make_float4(0.0f, 0.0f, 0.0f, 0.0f);
    for (int k0 = beg; k0 < end; k0 += 32) {
        int t = k0 + lane;
        int idx = (t < end) ? g_csr_src[t] : 0;
        int m = min(32, end - k0);
#pragma unroll 8
        for (int j = 0; j < m; j++) {
            int s = __shfl_sync(0xffffffffu, idx, j);
            uint2 raw = hh[s * 32 + lane];
            float2 f0 = __half22float2(*reinterpret_cast<__half2*>(&raw.x));
            float2 f1 = __half22float2(*reinterpret_cast<__half2*>(&raw.y));
            acc.x += f0.x; acc.y += f0.y; acc.z += f1.x; acc.w += f1.y;
        }
    }

    const float4* __restrict__ hws4 = reinterpret_cast<const float4*>(g_hws);
    float4 self = hws4[node * 32 + lane];
    float dinv = g_dinv[node];
    float4 b4 = reinterpret_cast<const float4*>(b)[lane];
    float4 o;
    o.x = dinv * (acc.x + 2.0f * self.x) + b4.x;
    o.y = dinv * (acc.y + 2.0f * self.y) + b4.y;
    o.z = dinv * (acc.z + 2.0f * self.z) + b4.z;
    o.w = dinv * (acc.w + 2.0f * self.w) + b4.w;
    reinterpret_cast<float4*>(g_agg)[node * 32 + lane] = o;
}

// column sums/sumsq over g_agg; block handles 128 rows (thread = column)
__global__ void stats_kernel() {
    const int c = threadIdx.x;
    const int r0 = blockIdx.x * 128;
    float s = 0.0f, sq = 0.0f;
    for (int i = 0; i < 128; i++) {
        int r = r0 + i;
        if (r >= N_NODES) break;
        float v = g_agg[r * D + c];
        s += v;
        sq += v * v;
    }
    atomicAdd(&g_colsum[c], s);
    atomicAdd(&g_colsq[c], sq);
}

__global__ void bn_final_kernel(const float* __restrict__ gamma,
                                const float* __restrict__ beta) {
    int c = threadIdx.x;
    float mean = g_colsum[c] * (1.0f / (float)N_NODES);
    float var = g_colsq[c] * (1.0f / (float)N_NODES) - mean * mean;
    float sc = gamma[c] * rsqrtf(var + BN_EPS);
    g_scale[c] = sc;
    g_shift[c] = beta[c] - mean * sc;
}

// final layer only: out = relu(agg*scale + shift)
__global__ void apply_kernel(float* __restrict__ out) {
    int idx = blockIdx.x * blockDim.x + threadIdx.x;
    if (idx >= N_NODES * D) return;
    int c = idx & (D - 1);
    float v = g_agg[idx] * g_scale[c] + g_shift[c];
    out[idx] = fmaxf(v, 0.0f);
}

// ---------------- launch ----------------
extern "C" void kernel_launch(void* const* d_in, const int* in_sizes, int n_in,
                              void* d_out, int out_size) {
    const float* x = (const float*)d_in[0];
    const void* ei = d_in[1];
    const float* W[3]  = {(const float*)d_in[2],  (const float*)d_in[6],  (const float*)d_in[10]};
    const float* bb[3] = {(const float*)d_in[3],  (const float*)d_in[7],  (const float*)d_in[11]};
    const float* gg[3] = {(const float*)d_in[4],  (const float*)d_in[8],  (const float*)d_in[12]};
    const float* be[3] = {(const float*)d_in[5],  (const float*)d_in[9],  (const float*)d_in[13]};
    float* out = (float*)d_out;

    const int eblocks = (N_EDGES + 255) / 256;
    const int gemm_blocks = (N_NODES + 63) / 64;
    const int agg_blocks = (N_NODES + 7) / 8;
    const int stats_blocks = (N_NODES + 127) / 128;
    const int app_blocks = (N_NODES * D + 255) / 256;

    detect_kernel<<<NB, 256>>>((const int*)ei);                 // 1
    convert_count_kernel<<<eblocks, 256>>>(ei);                 // 2
    scanA_kernel<<<NB, 256>>>();                                // 3 (writes dinv)
    gemm_kernel<<<gemm_blocks, 256>>>(x, W[0], 0);              // 4 <- ncu slot
    scanB_kernel<<<1, 256>>>();                                 // 5
    scanC_kernel<<<NB, 256>>>();                                // 6
    fill_kernel<<<eblocks, 256>>>();                            // 7

    for (int layer = 0; layer < 3; layer++) {
        if (layer > 0)
            gemm_kernel<<<gemm_blocks, 256>>>(x, W[layer], 1);
        aggregate_kernel<<<agg_blocks, 256>>>(bb[layer]);
        stats_kernel<<<stats_blocks, 128>>>();
        bn_final_kernel<<<1, D>>>(gg[layer], be[layer]);
    }
    apply_kernel<<<app_blocks, 256>>>(out);
}